// round 1
// baseline (speedup 1.0000x reference)
#include <cuda_runtime.h>

#define NN 100000
#define EE 1200000
#define DD 64
#define FF 192          // 3 windows * 64
#define OUTW 384        // 2 * (L+1) * 64

// Scratch (allocation-free contract: static __device__ arrays)
__device__ float g_HA[(size_t)NN * FF];   // ping
__device__ float g_HB[(size_t)NN * FF];   // pong
__device__ int   g_deg[NN];
__device__ int   g_rowptr[NN + 1];
__device__ int   g_cursor[NN];
__device__ int   g_ssrc[EE];

// ---------------- CSR build ----------------

__global__ void k_zero_deg() {
    int i = blockIdx.x * blockDim.x + threadIdx.x;
    if (i < NN) g_deg[i] = 0;
}

__global__ void k_hist(const int* __restrict__ dst) {
    int e = blockIdx.x * blockDim.x + threadIdx.x;
    if (e < EE) atomicAdd(&g_deg[dst[e]], 1);
}

// single block, 1024 threads: chunked exclusive scan of g_deg -> g_rowptr/g_cursor
__global__ void k_scan() {
    __shared__ int part[1024];
    const int CH = (NN + 1023) / 1024;   // 98
    int t = threadIdx.x;
    int base = t * CH;
    int s = 0;
    #pragma unroll 4
    for (int i = 0; i < CH; i++) {
        int idx = base + i;
        if (idx < NN) s += g_deg[idx];
    }
    part[t] = s;
    __syncthreads();
    // Hillis-Steele inclusive scan
    for (int off = 1; off < 1024; off <<= 1) {
        int v = (t >= off) ? part[t - off] : 0;
        __syncthreads();
        part[t] += v;
        __syncthreads();
    }
    int run = (t == 0) ? 0 : part[t - 1];
    for (int i = 0; i < CH; i++) {
        int idx = base + i;
        if (idx < NN) {
            g_rowptr[idx] = run;
            g_cursor[idx] = run;
            run += g_deg[idx];
        }
    }
    if (t == 1023) g_rowptr[NN] = part[1023];
}

__global__ void k_scatter(const int* __restrict__ src, const int* __restrict__ dst) {
    int e = blockIdx.x * blockDim.x + threadIdx.x;
    if (e < EE) {
        int p = atomicAdd(&g_cursor[dst[e]], 1);
        g_ssrc[p] = src[e];
    }
}

// ---------------- compute ----------------

__device__ __forceinline__ float warp_sum(float v) {
    #pragma unroll
    for (int o = 16; o > 0; o >>= 1) v += __shfl_xor_sync(0xffffffffu, v, o);
    return v;
}

// Layer 0: hn = LN(feature); H = [hn, hn*m1, hn*m2]; also write out cols [0:64) and [192:256)
__global__ void k_ln0(const float* __restrict__ feat, const int* __restrict__ age,
                      float* __restrict__ out) {
    int n = blockIdx.x * 8 + (threadIdx.x >> 5);   // grid = NN/8 exactly
    int t = threadIdx.x & 31;
    const float* f = feat + (size_t)n * DD;
    float a = f[t], b = f[t + 32];
    float s = warp_sum(a + b);
    float q = warp_sum(a * a + b * b);
    float mean = s * (1.0f / 64.0f);
    float var  = q * (1.0f / 64.0f) - mean * mean;
    float r = rsqrtf(var + 1e-5f);
    float ha = (a - mean) * r, hb = (b - mean) * r;
    int ag = age[n];
    float m1 = (ag >= 1) ? 1.0f : 0.0f;
    float m2 = (ag >= 2) ? 1.0f : 0.0f;
    float* H = g_HA + (size_t)n * FF;
    H[t]        = ha;       H[32 + t]  = hb;
    H[64 + t]   = ha * m1;  H[96 + t]  = hb * m1;
    H[128 + t]  = ha * m2;  H[160 + t] = hb * m2;
    float* o = out + (size_t)n * OUTW;
    o[t] = ha;  o[32 + t] = hb;
    float c = 1.0f - 0.5f * (m1 + m2);
    o[192 + t] = ha * c;  o[224 + t] = hb * c;
}

// SpMM over CSR + fused LN + ReLU + output write.
// layer==1: read g_HA, write g_HB ; layer==2: read g_HB (no state write needed)
__global__ void k_spmm(float* __restrict__ out, int layer) {
    int n = blockIdx.x * 8 + (threadIdx.x >> 5);   // grid = NN/8 exactly
    int t = threadIdx.x & 31;
    const float* __restrict__ Hin = (layer == 1) ? g_HA : g_HB;

    float acc0 = 0.f, acc1 = 0.f, acc2 = 0.f, acc3 = 0.f, acc4 = 0.f, acc5 = 0.f;
    int beg = g_rowptr[n], end = g_rowptr[n + 1];
    int e = beg;
    for (; e + 2 <= end; e += 2) {
        int s0 = g_ssrc[e], s1 = g_ssrc[e + 1];
        const float* r0 = Hin + (size_t)s0 * FF;
        const float* r1 = Hin + (size_t)s1 * FF;
        float a0 = r0[t],       b0 = r1[t];
        float a1 = r0[32 + t],  b1 = r1[32 + t];
        float a2 = r0[64 + t],  b2 = r1[64 + t];
        float a3 = r0[96 + t],  b3 = r1[96 + t];
        float a4 = r0[128 + t], b4 = r1[128 + t];
        float a5 = r0[160 + t], b5 = r1[160 + t];
        acc0 += a0 + b0; acc1 += a1 + b1; acc2 += a2 + b2;
        acc3 += a3 + b3; acc4 += a4 + b4; acc5 += a5 + b5;
    }
    if (e < end) {
        int s0 = g_ssrc[e];
        const float* r0 = Hin + (size_t)s0 * FF;
        acc0 += r0[t];       acc1 += r0[32 + t];
        acc2 += r0[64 + t];  acc3 += r0[96 + t];
        acc4 += r0[128 + t]; acc5 += r0[160 + t];
    }

    // LN + ReLU per 64-wide window
    float y0, y1, y2, y3, y4, y5;
    {
        float s = warp_sum(acc0 + acc1);
        float q = warp_sum(acc0 * acc0 + acc1 * acc1);
        float mean = s * (1.0f / 64.0f);
        float var  = q * (1.0f / 64.0f) - mean * mean;
        float r = rsqrtf(var + 1e-5f);
        y0 = fmaxf((acc0 - mean) * r, 0.f);
        y1 = fmaxf((acc1 - mean) * r, 0.f);
    }
    {
        float s = warp_sum(acc2 + acc3);
        float q = warp_sum(acc2 * acc2 + acc3 * acc3);
        float mean = s * (1.0f / 64.0f);
        float var  = q * (1.0f / 64.0f) - mean * mean;
        float r = rsqrtf(var + 1e-5f);
        y2 = fmaxf((acc2 - mean) * r, 0.f);
        y3 = fmaxf((acc3 - mean) * r, 0.f);
    }
    {
        float s = warp_sum(acc4 + acc5);
        float q = warp_sum(acc4 * acc4 + acc5 * acc5);
        float mean = s * (1.0f / 64.0f);
        float var  = q * (1.0f / 64.0f) - mean * mean;
        float r = rsqrtf(var + 1e-5f);
        y4 = fmaxf((acc4 - mean) * r, 0.f);
        y5 = fmaxf((acc5 - mean) * r, 0.f);
    }

    if (layer == 1) {
        float* Ho = g_HB + (size_t)n * FF;
        Ho[t] = y0;        Ho[32 + t]  = y1;
        Ho[64 + t] = y2;   Ho[96 + t]  = y3;
        Ho[128 + t] = y4;  Ho[160 + t] = y5;
    }

    float* o = out + (size_t)n * OUTW + layer * 64;
    o[t]       = y0;
    o[32 + t]  = y1;
    o[192 + t]      = y0 - 0.5f * (y2 + y4);
    o[192 + 32 + t] = y1 - 0.5f * (y3 + y5);
}

// ---------------- launch ----------------

extern "C" void kernel_launch(void* const* d_in, const int* in_sizes, int n_in,
                              void* d_out, int out_size) {
    const float* feature = (const float*)d_in[0];
    const int*   age     = (const int*)d_in[1];
    const int*   src     = (const int*)d_in[2];
    const int*   dst     = (const int*)d_in[3];
    float* out = (float*)d_out;

    (void)in_sizes; (void)n_in; (void)out_size;

    // CSR build (by destination)
    k_zero_deg<<<(NN + 255) / 256, 256>>>();
    k_hist<<<(EE + 255) / 256, 256>>>(dst);
    k_scan<<<1, 1024>>>();
    k_scatter<<<(EE + 255) / 256, 256>>>(src, dst);

    // layer 0 (LN + window masks + first output block)
    k_ln0<<<NN / 8, 256>>>(feature, age, out);

    // layers 1..2 (SpMM + LN + ReLU fused, batched over 3 windows)
    k_spmm<<<NN / 8, 256>>>(out, 1);
    k_spmm<<<NN / 8, 256>>>(out, 2);
}

// round 3
// speedup vs baseline: 1.1293x; 1.1293x over previous
#include <cuda_runtime.h>

#define NN 100000
#define EE 1200000
#define DD 64
#define FF 192          // 3 windows * 64
#define OUTW 384        // 2 * (L+1) * 64

// Scratch (allocation-free contract: static __device__ arrays)
__device__ float  g_HN[(size_t)NN * DD];   // LN(feature), window-0 state
__device__ float2 g_M[NN];                 // (m1, m2) per node
__device__ float  g_HB[(size_t)NN * FF];   // layer-1 output state (3 windows)
__device__ int    g_deg[NN];
__device__ int    g_rowptr[NN + 1];
__device__ int    g_cursor[NN];
__device__ int    g_ssrc[EE];

// ---------------- CSR build ----------------

__global__ void k_zero_deg() {
    int i = blockIdx.x * blockDim.x + threadIdx.x;
    if (i < NN) g_deg[i] = 0;
}

__global__ void k_hist(const int* __restrict__ dst) {
    int e = blockIdx.x * blockDim.x + threadIdx.x;
    if (e < EE) atomicAdd(&g_deg[dst[e]], 1);
}

// single block, 1024 threads: chunked exclusive scan of g_deg -> g_rowptr/g_cursor
__global__ void k_scan() {
    __shared__ int part[1024];
    const int CH = (NN + 1023) / 1024;   // 98
    int t = threadIdx.x;
    int base = t * CH;
    int s = 0;
    #pragma unroll 4
    for (int i = 0; i < CH; i++) {
        int idx = base + i;
        if (idx < NN) s += g_deg[idx];
    }
    part[t] = s;
    __syncthreads();
    for (int off = 1; off < 1024; off <<= 1) {
        int v = (t >= off) ? part[t - off] : 0;
        __syncthreads();
        part[t] += v;
        __syncthreads();
    }
    int run = (t == 0) ? 0 : part[t - 1];
    for (int i = 0; i < CH; i++) {
        int idx = base + i;
        if (idx < NN) {
            g_rowptr[idx] = run;
            g_cursor[idx] = run;
            run += g_deg[idx];
        }
    }
    if (t == 1023) g_rowptr[NN] = part[1023];
}

__global__ void k_scatter(const int* __restrict__ src, const int* __restrict__ dst) {
    int e = blockIdx.x * blockDim.x + threadIdx.x;
    if (e < EE) {
        int p = atomicAdd(&g_cursor[dst[e]], 1);
        g_ssrc[p] = src[e];
    }
}

// ---------------- compute ----------------

__device__ __forceinline__ float warp_sum(float v) {
    #pragma unroll
    for (int o = 16; o > 0; o >>= 1) v += __shfl_xor_sync(0xffffffffu, v, o);
    return v;
}

// Layer 0: hn = LN(feature); store hn + masks; write out cols [0:64) and [192:256)
__global__ void k_ln0(const float* __restrict__ feat, const int* __restrict__ age,
                      float* __restrict__ out) {
    int n = blockIdx.x * 8 + (threadIdx.x >> 5);   // grid = NN/8 exactly
    int t = threadIdx.x & 31;
    const float* f = feat + (size_t)n * DD;
    float a = f[t], b = f[t + 32];
    float s = warp_sum(a + b);
    float q = warp_sum(a * a + b * b);
    float mean = s * (1.0f / 64.0f);
    float var  = q * (1.0f / 64.0f) - mean * mean;
    float r = rsqrtf(var + 1e-5f);
    float ha = (a - mean) * r, hb = (b - mean) * r;
    int ag = age[n];
    float m1 = (ag >= 1) ? 1.0f : 0.0f;
    float m2 = (ag >= 2) ? 1.0f : 0.0f;
    float* H = g_HN + (size_t)n * DD;
    H[t] = ha;  H[32 + t] = hb;
    if (t == 0) g_M[n] = make_float2(m1, m2);
    float* o = out + (size_t)n * OUTW;
    o[t] = ha;  o[32 + t] = hb;
    float c = 1.0f - 0.5f * (m1 + m2);
    o[192 + t] = ha * c;  o[224 + t] = hb * c;
}

// Layer 1 SpMM: gathers hn rows (64-wide) + per-source masks; expands to 3 windows
// in registers. Fused LN + ReLU + state write + output write.
__global__ void k_spmm1(float* __restrict__ out) {
    int n = blockIdx.x * 8 + (threadIdx.x >> 5);   // grid = NN/8 exactly
    int t = threadIdx.x & 31;

    float acc0 = 0.f, acc1 = 0.f;   // window 0 (cols t, t+32)
    float acc2 = 0.f, acc3 = 0.f;   // window 1
    float acc4 = 0.f, acc5 = 0.f;   // window 2
    int beg = g_rowptr[n], end = g_rowptr[n + 1];
    int e = beg;
    for (; e + 4 <= end; e += 4) {
        int s0 = __ldg(&g_ssrc[e]);
        int s1 = __ldg(&g_ssrc[e + 1]);
        int s2 = __ldg(&g_ssrc[e + 2]);
        int s3 = __ldg(&g_ssrc[e + 3]);
        const float* r0 = g_HN + (size_t)s0 * DD;
        const float* r1 = g_HN + (size_t)s1 * DD;
        const float* r2 = g_HN + (size_t)s2 * DD;
        const float* r3 = g_HN + (size_t)s3 * DD;
        float2 m0 = __ldg(&g_M[s0]);
        float2 m1v = __ldg(&g_M[s1]);
        float2 m2v = __ldg(&g_M[s2]);
        float2 m3v = __ldg(&g_M[s3]);
        float a0 = __ldg(&r0[t]), b0 = __ldg(&r0[32 + t]);
        float a1 = __ldg(&r1[t]), b1 = __ldg(&r1[32 + t]);
        float a2 = __ldg(&r2[t]), b2 = __ldg(&r2[32 + t]);
        float a3 = __ldg(&r3[t]), b3 = __ldg(&r3[32 + t]);
        acc0 += a0 + a1 + a2 + a3;
        acc1 += b0 + b1 + b2 + b3;
        acc2 += a0 * m0.x + a1 * m1v.x + a2 * m2v.x + a3 * m3v.x;
        acc3 += b0 * m0.x + b1 * m1v.x + b2 * m2v.x + b3 * m3v.x;
        acc4 += a0 * m0.y + a1 * m1v.y + a2 * m2v.y + a3 * m3v.y;
        acc5 += b0 * m0.y + b1 * m1v.y + b2 * m2v.y + b3 * m3v.y;
    }
    for (; e < end; e++) {
        int s0 = __ldg(&g_ssrc[e]);
        const float* r0 = g_HN + (size_t)s0 * DD;
        float a0 = __ldg(&r0[t]), b0 = __ldg(&r0[32 + t]);
        float2 m0 = __ldg(&g_M[s0]);
        acc0 += a0;          acc1 += b0;
        acc2 += a0 * m0.x;   acc3 += b0 * m0.x;
        acc4 += a0 * m0.y;   acc5 += b0 * m0.y;
    }

    // LN + ReLU per 64-wide window
    float y0, y1, y2, y3, y4, y5;
    {
        float s = warp_sum(acc0 + acc1);
        float q = warp_sum(acc0 * acc0 + acc1 * acc1);
        float mean = s * (1.0f / 64.0f);
        float var  = q * (1.0f / 64.0f) - mean * mean;
        float r = rsqrtf(var + 1e-5f);
        y0 = fmaxf((acc0 - mean) * r, 0.f);
        y1 = fmaxf((acc1 - mean) * r, 0.f);
    }
    {
        float s = warp_sum(acc2 + acc3);
        float q = warp_sum(acc2 * acc2 + acc3 * acc3);
        float mean = s * (1.0f / 64.0f);
        float var  = q * (1.0f / 64.0f) - mean * mean;
        float r = rsqrtf(var + 1e-5f);
        y2 = fmaxf((acc2 - mean) * r, 0.f);
        y3 = fmaxf((acc3 - mean) * r, 0.f);
    }
    {
        float s = warp_sum(acc4 + acc5);
        float q = warp_sum(acc4 * acc4 + acc5 * acc5);
        float mean = s * (1.0f / 64.0f);
        float var  = q * (1.0f / 64.0f) - mean * mean;
        float r = rsqrtf(var + 1e-5f);
        y4 = fmaxf((acc4 - mean) * r, 0.f);
        y5 = fmaxf((acc5 - mean) * r, 0.f);
    }

    float* Ho = g_HB + (size_t)n * FF;
    Ho[t] = y0;        Ho[32 + t]  = y1;
    Ho[64 + t] = y2;   Ho[96 + t]  = y3;
    Ho[128 + t] = y4;  Ho[160 + t] = y5;

    float* o = out + (size_t)n * OUTW + 64;
    o[t]       = y0;
    o[32 + t]  = y1;
    o[192 + t]      = y0 - 0.5f * (y2 + y4);
    o[192 + 32 + t] = y1 - 0.5f * (y3 + y5);
}

// Layer 2 SpMM over the full 192-wide state. Fused LN + ReLU + output write.
__global__ void k_spmm2(float* __restrict__ out) {
    int n = blockIdx.x * 8 + (threadIdx.x >> 5);   // grid = NN/8 exactly
    int t = threadIdx.x & 31;

    float acc0 = 0.f, acc1 = 0.f, acc2 = 0.f, acc3 = 0.f, acc4 = 0.f, acc5 = 0.f;
    int beg = g_rowptr[n], end = g_rowptr[n + 1];
    int e = beg;
    for (; e + 2 <= end; e += 2) {
        int s0 = __ldg(&g_ssrc[e]);
        int s1 = __ldg(&g_ssrc[e + 1]);
        const float* r0 = g_HB + (size_t)s0 * FF;
        const float* r1 = g_HB + (size_t)s1 * FF;
        float a0 = __ldg(&r0[t]),       b0 = __ldg(&r1[t]);
        float a1 = __ldg(&r0[32 + t]),  b1 = __ldg(&r1[32 + t]);
        float a2 = __ldg(&r0[64 + t]),  b2 = __ldg(&r1[64 + t]);
        float a3 = __ldg(&r0[96 + t]),  b3 = __ldg(&r1[96 + t]);
        float a4 = __ldg(&r0[128 + t]), b4 = __ldg(&r1[128 + t]);
        float a5 = __ldg(&r0[160 + t]), b5 = __ldg(&r1[160 + t]);
        acc0 += a0 + b0; acc1 += a1 + b1; acc2 += a2 + b2;
        acc3 += a3 + b3; acc4 += a4 + b4; acc5 += a5 + b5;
    }
    if (e < end) {
        int s0 = __ldg(&g_ssrc[e]);
        const float* r0 = g_HB + (size_t)s0 * FF;
        acc0 += __ldg(&r0[t]);       acc1 += __ldg(&r0[32 + t]);
        acc2 += __ldg(&r0[64 + t]);  acc3 += __ldg(&r0[96 + t]);
        acc4 += __ldg(&r0[128 + t]); acc5 += __ldg(&r0[160 + t]);
    }

    float y0, y1, y2, y3, y4, y5;
    {
        float s = warp_sum(acc0 + acc1);
        float q = warp_sum(acc0 * acc0 + acc1 * acc1);
        float mean = s * (1.0f / 64.0f);
        float var  = q * (1.0f / 64.0f) - mean * mean;
        float r = rsqrtf(var + 1e-5f);
        y0 = fmaxf((acc0 - mean) * r, 0.f);
        y1 = fmaxf((acc1 - mean) * r, 0.f);
    }
    {
        float s = warp_sum(acc2 + acc3);
        float q = warp_sum(acc2 * acc2 + acc3 * acc3);
        float mean = s * (1.0f / 64.0f);
        float var  = q * (1.0f / 64.0f) - mean * mean;
        float r = rsqrtf(var + 1e-5f);
        y2 = fmaxf((acc2 - mean) * r, 0.f);
        y3 = fmaxf((acc3 - mean) * r, 0.f);
    }
    {
        float s = warp_sum(acc4 + acc5);
        float q = warp_sum(acc4 * acc4 + acc5 * acc5);
        float mean = s * (1.0f / 64.0f);
        float var  = q * (1.0f / 64.0f) - mean * mean;
        float r = rsqrtf(var + 1e-5f);
        y4 = fmaxf((acc4 - mean) * r, 0.f);
        y5 = fmaxf((acc5 - mean) * r, 0.f);
    }

    float* o = out + (size_t)n * OUTW + 128;
    o[t]       = y0;
    o[32 + t]  = y1;
    o[192 + t]      = y0 - 0.5f * (y2 + y4);
    o[192 + 32 + t] = y1 - 0.5f * (y3 + y5);
}

// ---------------- launch ----------------

extern "C" void kernel_launch(void* const* d_in, const int* in_sizes, int n_in,
                              void* d_out, int out_size) {
    const float* feature = (const float*)d_in[0];
    const int*   age     = (const int*)d_in[1];
    const int*   src     = (const int*)d_in[2];
    const int*   dst     = (const int*)d_in[3];
    float* out = (float*)d_out;

    (void)in_sizes; (void)n_in; (void)out_size;

    // CSR build (by destination)
    k_zero_deg<<<(NN + 255) / 256, 256>>>();
    k_hist<<<(EE + 255) / 256, 256>>>(dst);
    k_scan<<<1, 1024>>>();
    k_scatter<<<(EE + 255) / 256, 256>>>(src, dst);

    // layer 0 (LN + masks + first output block)
    k_ln0<<<NN / 8, 256>>>(feature, age, out);

    // layer 1 (compact 64-wide gather, 3-window expansion in registers)
    k_spmm1<<<NN / 8, 256>>>(out);

    // layer 2 (full 192-wide gather)
    k_spmm2<<<NN / 8, 256>>>(out);
}

// round 4
// speedup vs baseline: 1.2721x; 1.1265x over previous
#include <cuda_runtime.h>
#include <cuda_fp16.h>

#define NN 100000
#define EE 1200000

// Scratch (allocation-free contract: static __device__ arrays)
__device__ __half2 g_HN[(size_t)NN * 32];   // LN(feature), 64 cols as 32 half2
__device__ float2  g_M[NN];                 // (m1, m2) per node
__device__ __half2 g_HB[(size_t)NN * 96];   // layer-1 state, 3 windows x 32 half2
__device__ int     g_deg[NN];
__device__ int     g_rowptr[NN + 1];
__device__ int     g_cursor[NN];
__device__ int     g_ssrc[EE];

// ---------------- CSR build ----------------

__global__ void k_zero_deg() {
    int i = blockIdx.x * blockDim.x + threadIdx.x;
    if (i < NN) g_deg[i] = 0;
}

__global__ void k_hist(const int* __restrict__ dst) {
    int e = blockIdx.x * blockDim.x + threadIdx.x;
    if (e < EE) atomicAdd(&g_deg[dst[e]], 1);
}

__global__ void k_scan() {
    __shared__ int part[1024];
    const int CH = (NN + 1023) / 1024;   // 98
    int t = threadIdx.x;
    int base = t * CH;
    int s = 0;
    #pragma unroll 4
    for (int i = 0; i < CH; i++) {
        int idx = base + i;
        if (idx < NN) s += g_deg[idx];
    }
    part[t] = s;
    __syncthreads();
    for (int off = 1; off < 1024; off <<= 1) {
        int v = (t >= off) ? part[t - off] : 0;
        __syncthreads();
        part[t] += v;
        __syncthreads();
    }
    int run = (t == 0) ? 0 : part[t - 1];
    for (int i = 0; i < CH; i++) {
        int idx = base + i;
        if (idx < NN) {
            g_rowptr[idx] = run;
            g_cursor[idx] = run;
            run += g_deg[idx];
        }
    }
    if (t == 1023) g_rowptr[NN] = part[1023];
}

__global__ void k_scatter(const int* __restrict__ src, const int* __restrict__ dst) {
    int e = blockIdx.x * blockDim.x + threadIdx.x;
    if (e < EE) {
        int p = atomicAdd(&g_cursor[dst[e]], 1);
        g_ssrc[p] = src[e];
    }
}

// ---------------- compute ----------------

__device__ __forceinline__ float warp_sum(float v) {
    #pragma unroll
    for (int o = 16; o > 0; o >>= 1) v += __shfl_xor_sync(0xffffffffu, v, o);
    return v;
}

// lane t owns cols (2t, 2t+1) everywhere below; out viewed as float2 rows of 192.

__global__ void k_ln0(const float* __restrict__ feat, const int* __restrict__ age,
                      float2* __restrict__ out) {
    int n = blockIdx.x * 8 + (threadIdx.x >> 5);   // grid = NN/8 exactly
    int t = threadIdx.x & 31;
    const float2* f = (const float2*)(feat + (size_t)n * 64);
    float2 v = __ldg(&f[t]);
    float s = warp_sum(v.x + v.y);
    float q = warp_sum(v.x * v.x + v.y * v.y);
    float mean = s * (1.0f / 64.0f);
    float var  = q * (1.0f / 64.0f) - mean * mean;
    float r = rsqrtf(var + 1e-5f);
    float ha = (v.x - mean) * r, hb = (v.y - mean) * r;
    int ag = __ldg(&age[n]);
    float m1 = (ag >= 1) ? 1.0f : 0.0f;
    float m2 = (ag >= 2) ? 1.0f : 0.0f;
    g_HN[(size_t)n * 32 + t] = __floats2half2_rn(ha, hb);
    if (t == 0) g_M[n] = make_float2(m1, m2);
    float2* o = out + (size_t)n * 192;
    o[t] = make_float2(ha, hb);
    float c = 1.0f - 0.5f * (m1 + m2);
    o[96 + t] = make_float2(ha * c, hb * c);
}

// Layer 1: gather 64-wide fp16 rows + masks, expand 3 windows in registers.
__global__ void k_spmm1(float2* __restrict__ out) {
    int n = blockIdx.x * 8 + (threadIdx.x >> 5);
    int t = threadIdx.x & 31;

    float w0x = 0.f, w0y = 0.f, w1x = 0.f, w1y = 0.f, w2x = 0.f, w2y = 0.f;
    int beg = g_rowptr[n], end = g_rowptr[n + 1];
    int e = beg;
    for (; e + 4 <= end; e += 4) {
        int s0 = __ldg(&g_ssrc[e]);
        int s1 = __ldg(&g_ssrc[e + 1]);
        int s2 = __ldg(&g_ssrc[e + 2]);
        int s3 = __ldg(&g_ssrc[e + 3]);
        __half2 h0 = __ldg(&g_HN[(size_t)s0 * 32 + t]);
        __half2 h1 = __ldg(&g_HN[(size_t)s1 * 32 + t]);
        __half2 h2 = __ldg(&g_HN[(size_t)s2 * 32 + t]);
        __half2 h3 = __ldg(&g_HN[(size_t)s3 * 32 + t]);
        float2 m0 = __ldg(&g_M[s0]);
        float2 m1v = __ldg(&g_M[s1]);
        float2 m2v = __ldg(&g_M[s2]);
        float2 m3v = __ldg(&g_M[s3]);
        float2 f0 = __half22float2(h0);
        float2 f1 = __half22float2(h1);
        float2 f2 = __half22float2(h2);
        float2 f3 = __half22float2(h3);
        w0x += f0.x + f1.x + f2.x + f3.x;
        w0y += f0.y + f1.y + f2.y + f3.y;
        w1x += f0.x * m0.x + f1.x * m1v.x + f2.x * m2v.x + f3.x * m3v.x;
        w1y += f0.y * m0.x + f1.y * m1v.x + f2.y * m2v.x + f3.y * m3v.x;
        w2x += f0.x * m0.y + f1.x * m1v.y + f2.x * m2v.y + f3.x * m3v.y;
        w2y += f0.y * m0.y + f1.y * m1v.y + f2.y * m2v.y + f3.y * m3v.y;
    }
    for (; e < end; e++) {
        int s0 = __ldg(&g_ssrc[e]);
        float2 f0 = __half22float2(__ldg(&g_HN[(size_t)s0 * 32 + t]));
        float2 m0 = __ldg(&g_M[s0]);
        w0x += f0.x;        w0y += f0.y;
        w1x += f0.x * m0.x; w1y += f0.y * m0.x;
        w2x += f0.x * m0.y; w2y += f0.y * m0.y;
    }

    float y0x, y0y, y1x, y1y, y2x, y2y;
    {
        float s = warp_sum(w0x + w0y);
        float q = warp_sum(w0x * w0x + w0y * w0y);
        float mean = s * (1.0f / 64.0f);
        float var  = q * (1.0f / 64.0f) - mean * mean;
        float r = rsqrtf(var + 1e-5f);
        y0x = fmaxf((w0x - mean) * r, 0.f);
        y0y = fmaxf((w0y - mean) * r, 0.f);
    }
    {
        float s = warp_sum(w1x + w1y);
        float q = warp_sum(w1x * w1x + w1y * w1y);
        float mean = s * (1.0f / 64.0f);
        float var  = q * (1.0f / 64.0f) - mean * mean;
        float r = rsqrtf(var + 1e-5f);
        y1x = fmaxf((w1x - mean) * r, 0.f);
        y1y = fmaxf((w1y - mean) * r, 0.f);
    }
    {
        float s = warp_sum(w2x + w2y);
        float q = warp_sum(w2x * w2x + w2y * w2y);
        float mean = s * (1.0f / 64.0f);
        float var  = q * (1.0f / 64.0f) - mean * mean;
        float r = rsqrtf(var + 1e-5f);
        y2x = fmaxf((w2x - mean) * r, 0.f);
        y2y = fmaxf((w2y - mean) * r, 0.f);
    }

    __half2* Ho = g_HB + (size_t)n * 96;
    Ho[t]      = __floats2half2_rn(y0x, y0y);
    Ho[32 + t] = __floats2half2_rn(y1x, y1y);
    Ho[64 + t] = __floats2half2_rn(y2x, y2y);

    float2* o = out + (size_t)n * 192;
    o[32 + t]  = make_float2(y0x, y0y);
    o[128 + t] = make_float2(y0x - 0.5f * (y1x + y2x), y0y - 0.5f * (y1y + y2y));
}

// Layer 2: gather 192-wide fp16 rows (3 half2 loads per edge per lane).
__global__ void k_spmm2(float2* __restrict__ out) {
    int n = blockIdx.x * 8 + (threadIdx.x >> 5);
    int t = threadIdx.x & 31;

    float w0x = 0.f, w0y = 0.f, w1x = 0.f, w1y = 0.f, w2x = 0.f, w2y = 0.f;
    int beg = g_rowptr[n], end = g_rowptr[n + 1];
    int e = beg;
    for (; e + 4 <= end; e += 4) {
        int s0 = __ldg(&g_ssrc[e]);
        int s1 = __ldg(&g_ssrc[e + 1]);
        int s2 = __ldg(&g_ssrc[e + 2]);
        int s3 = __ldg(&g_ssrc[e + 3]);
        const __half2* r0 = g_HB + (size_t)s0 * 96;
        const __half2* r1 = g_HB + (size_t)s1 * 96;
        const __half2* r2 = g_HB + (size_t)s2 * 96;
        const __half2* r3 = g_HB + (size_t)s3 * 96;
        __half2 a0 = __ldg(&r0[t]),      a1 = __ldg(&r1[t]),      a2 = __ldg(&r2[t]),      a3 = __ldg(&r3[t]);
        __half2 b0 = __ldg(&r0[32 + t]), b1 = __ldg(&r1[32 + t]), b2 = __ldg(&r2[32 + t]), b3 = __ldg(&r3[32 + t]);
        __half2 c0 = __ldg(&r0[64 + t]), c1 = __ldg(&r1[64 + t]), c2 = __ldg(&r2[64 + t]), c3 = __ldg(&r3[64 + t]);
        float2 fa0 = __half22float2(a0), fa1 = __half22float2(a1), fa2 = __half22float2(a2), fa3 = __half22float2(a3);
        float2 fb0 = __half22float2(b0), fb1 = __half22float2(b1), fb2 = __half22float2(b2), fb3 = __half22float2(b3);
        float2 fc0 = __half22float2(c0), fc1 = __half22float2(c1), fc2 = __half22float2(c2), fc3 = __half22float2(c3);
        w0x += fa0.x + fa1.x + fa2.x + fa3.x;
        w0y += fa0.y + fa1.y + fa2.y + fa3.y;
        w1x += fb0.x + fb1.x + fb2.x + fb3.x;
        w1y += fb0.y + fb1.y + fb2.y + fb3.y;
        w2x += fc0.x + fc1.x + fc2.x + fc3.x;
        w2y += fc0.y + fc1.y + fc2.y + fc3.y;
    }
    for (; e < end; e++) {
        int s0 = __ldg(&g_ssrc[e]);
        const __half2* r0 = g_HB + (size_t)s0 * 96;
        float2 fa = __half22float2(__ldg(&r0[t]));
        float2 fb = __half22float2(__ldg(&r0[32 + t]));
        float2 fc = __half22float2(__ldg(&r0[64 + t]));
        w0x += fa.x; w0y += fa.y;
        w1x += fb.x; w1y += fb.y;
        w2x += fc.x; w2y += fc.y;
    }

    float y0x, y0y, y1x, y1y, y2x, y2y;
    {
        float s = warp_sum(w0x + w0y);
        float q = warp_sum(w0x * w0x + w0y * w0y);
        float mean = s * (1.0f / 64.0f);
        float var  = q * (1.0f / 64.0f) - mean * mean;
        float r = rsqrtf(var + 1e-5f);
        y0x = fmaxf((w0x - mean) * r, 0.f);
        y0y = fmaxf((w0y - mean) * r, 0.f);
    }
    {
        float s = warp_sum(w1x + w1y);
        float q = warp_sum(w1x * w1x + w1y * w1y);
        float mean = s * (1.0f / 64.0f);
        float var  = q * (1.0f / 64.0f) - mean * mean;
        float r = rsqrtf(var + 1e-5f);
        y1x = fmaxf((w1x - mean) * r, 0.f);
        y1y = fmaxf((w1y - mean) * r, 0.f);
    }
    {
        float s = warp_sum(w2x + w2y);
        float q = warp_sum(w2x * w2x + w2y * w2y);
        float mean = s * (1.0f / 64.0f);
        float var  = q * (1.0f / 64.0f) - mean * mean;
        float r = rsqrtf(var + 1e-5f);
        y2x = fmaxf((w2x - mean) * r, 0.f);
        y2y = fmaxf((w2y - mean) * r, 0.f);
    }

    float2* o = out + (size_t)n * 192;
    o[64 + t]  = make_float2(y0x, y0y);
    o[160 + t] = make_float2(y0x - 0.5f * (y1x + y2x), y0y - 0.5f * (y1y + y2y));
}

// ---------------- launch ----------------

extern "C" void kernel_launch(void* const* d_in, const int* in_sizes, int n_in,
                              void* d_out, int out_size) {
    const float* feature = (const float*)d_in[0];
    const int*   age     = (const int*)d_in[1];
    const int*   src     = (const int*)d_in[2];
    const int*   dst     = (const int*)d_in[3];
    float2* out = (float2*)d_out;

    (void)in_sizes; (void)n_in; (void)out_size;

    k_zero_deg<<<(NN + 255) / 256, 256>>>();
    k_hist<<<(EE + 255) / 256, 256>>>(dst);
    k_scan<<<1, 1024>>>();
    k_scatter<<<(EE + 255) / 256, 256>>>(src, dst);

    k_ln0<<<NN / 8, 256>>>(feature, age, out);
    k_spmm1<<<NN / 8, 256>>>(out);
    k_spmm2<<<NN / 8, 256>>>(out);
}